// round 2
// baseline (speedup 1.0000x reference)
#include <cuda_runtime.h>

// Problem constants (fixed shapes for this problem)
#define NN 100000
#define EE 3200000

// ---------------------------------------------------------------------------
// Scratch: one big __device__ array, carved by constexpr offsets (floats).
//   cnt   [4N]  (int, aliased)      @ 0
//   dinv  [4N]                      @ 400000
//   u1..u4[N*16], u5[N*12]          @ 800000 .. 8400000
//   agg1..agg4[N*16], agg5[N*12]    @ 8400000 .. 16000000   (zeroed each call)
//   hp, hc1, hc2, hf [N*16]         @ 16000000 .. 22400000
// ---------------------------------------------------------------------------
__device__ float g_scratch[22400000];

static const long O_CNT  = 0;
static const long O_DINV = 400000;
static const long O_U1   = 800000;
static const long O_U2   = 2400000;
static const long O_U3   = 4000000;
static const long O_U4   = 5600000;
static const long O_U5   = 7200000;   // stride 12
static const long O_A1   = 8400000;
static const long O_A2   = 10000000;
static const long O_A3   = 11600000;
static const long O_A4   = 13200000;
static const long O_A5   = 14800000;  // stride 12
static const long O_HP   = 16000000;
static const long O_HC1  = 17600000;
static const long O_HC2  = 19200000;
static const long O_HF   = 20800000;

// ---------------------------------------------------------------------------
// Zero: cnt (400000 floats-worth of ints = 100000 float4) + agg region
// (7,600,000 floats = 1,900,000 float4). Total 2,000,000 float4 stores.
// ---------------------------------------------------------------------------
__global__ void zero_k(float* __restrict__ S) {
    int i = blockIdx.x * 256 + threadIdx.x;
    if (i >= 2000000) return;
    long w = (i < 100000) ? (long)i : (long)(i - 100000) + 2100000;
    ((float4*)S)[w] = make_float4(0.f, 0.f, 0.f, 0.f);
}

// ---------------------------------------------------------------------------
// Fused degree histogram over dst for all 4 graphs in one launch.
// Edge weights are all 1; deg = cnt + 1 added in dinv_k.
// ---------------------------------------------------------------------------
__global__ void count4_k(const int* __restrict__ d0, const int* __restrict__ d1,
                         const int* __restrict__ d2, const int* __restrict__ d3,
                         int* __restrict__ cnt) {
    long t = (long)blockIdx.x * 256 + threadIdx.x;
    if (t >= 4L * EE) return;
    int g = (int)(t / EE);
    int e = (int)(t - (long)g * EE);
    const int* d = (g == 0) ? d0 : (g == 1) ? d1 : (g == 2) ? d2 : d3;
    atomicAdd(&cnt[g * NN + __ldg(d + e)], 1);
}

__global__ void dinv_k(const int* __restrict__ cnt, float* __restrict__ dinv) {
    int i = blockIdx.x * 256 + threadIdx.x;
    if (i < 4 * NN) dinv[i] = rsqrtf((float)cnt[i] + 1.0f);
}

// ---------------------------------------------------------------------------
// GEMM: U[n][f] = dinv[n] * sum_k X[n][k] * W[k][f],  H=16, F in {128,129,130}
// 64 nodes / 64 threads per block, full row staged in smem (padded to 132).
// ---------------------------------------------------------------------------
template<int F>
__global__ __launch_bounds__(64) void gemm_k(const float* __restrict__ X,
                                             const float* __restrict__ W,
                                             const float* __restrict__ dinv,
                                             float* __restrict__ U) {
    constexpr int FP = 132;
    __shared__ float xs[64 * FP];   // 33792 B
    __shared__ float ws[FP * 16];   //  8448 B
    const int tid = threadIdx.x;
    const int node0 = blockIdx.x * 64;

    // Stage W (zero-padded rows F..FP)
    for (int i = tid; i < FP * 16; i += 64)
        ws[i] = (i < F * 16) ? W[i] : 0.f;

    // Stage X rows (coalesced over the block's contiguous span)
    int valid = NN - node0; if (valid > 64) valid = 64;
    const int lim = valid * F;
    for (int i = tid; i < lim; i += 64) {
        int r = i / F;
        int k = i - r * F;
        xs[r * FP + k] = X[(long)node0 * F + i];
    }
    // Zero the per-row padding columns [F, FP)
    constexpr int PAD = FP - F;
    for (int i = tid; i < 64 * PAD; i += 64) {
        int r = i / PAD;
        int c = i - r * PAD;
        xs[r * FP + F + c] = 0.f;
    }
    __syncthreads();

    const int n = node0 + tid;
    if (n >= NN) return;

    float acc[16];
#pragma unroll
    for (int f = 0; f < 16; f++) acc[f] = 0.f;

    const float* xr = xs + tid * FP;
#pragma unroll 4
    for (int k = 0; k < FP; k += 4) {
        float4 xv = *(const float4*)(xr + k);
#pragma unroll
        for (int j = 0; j < 4; j++) {
            float xk = (j == 0) ? xv.x : (j == 1) ? xv.y : (j == 2) ? xv.z : xv.w;
            const float4* wr = (const float4*)(ws + (k + j) * 16);
            float4 w0 = wr[0], w1 = wr[1], w2 = wr[2], w3 = wr[3];
            acc[0]  += xk * w0.x; acc[1]  += xk * w0.y; acc[2]  += xk * w0.z; acc[3]  += xk * w0.w;
            acc[4]  += xk * w1.x; acc[5]  += xk * w1.y; acc[6]  += xk * w1.z; acc[7]  += xk * w1.w;
            acc[8]  += xk * w2.x; acc[9]  += xk * w2.y; acc[10] += xk * w2.z; acc[11] += xk * w2.w;
            acc[12] += xk * w3.x; acc[13] += xk * w3.y; acc[14] += xk * w3.z; acc[15] += xk * w3.w;
        }
    }

    const float dv = dinv[n];
    float4* up = (float4*)(U + (long)n * 16);
    up[0] = make_float4(dv * acc[0],  dv * acc[1],  dv * acc[2],  dv * acc[3]);
    up[1] = make_float4(dv * acc[4],  dv * acc[5],  dv * acc[6],  dv * acc[7]);
    up[2] = make_float4(dv * acc[8],  dv * acc[9],  dv * acc[10], dv * acc[11]);
    up[3] = make_float4(dv * acc[12], dv * acc[13], dv * acc[14], dv * acc[15]);
}

// ---------------------------------------------------------------------------
// Edge scatter: agg[dst] += u[src]  (rows of ST floats; NQ float4 quarters).
// 4 lanes per edge; lane q=0 loads src/dst once and broadcasts via shfl.
// Coalesced 64B row reads + float4 vector atomics (sm_90+).
// ---------------------------------------------------------------------------
template<int ST, int NQ>
__global__ void scatter_k(const int* __restrict__ src, const int* __restrict__ dst,
                          const float* __restrict__ u, float* __restrict__ agg) {
    int t = blockIdx.x * 256 + threadIdx.x;
    int e = t >> 2;
    int q = t & 3;
    if (e >= EE) return;
    int s = 0, d = 0;
    if (q == 0) { s = __ldg(src + e); d = __ldg(dst + e); }
    // broadcast from the group leader lane (lane_id & ~3)
    int leader = (threadIdx.x & 31) & ~3;
    s = __shfl_sync(0xFFFFFFFFu, s, leader);
    d = __shfl_sync(0xFFFFFFFFu, d, leader);
    if (q >= NQ) return;
    float4 v = *(const float4*)(u + (long)s * ST + q * 4);
    atomicAdd((float4*)(agg + (long)d * ST + q * 4), v);
}

// ---------------------------------------------------------------------------
// Per-node epilogue: h = dinv*(agg + u) + b [+ relu(rA) + rA] [+ rB]
// ---------------------------------------------------------------------------
template<bool HAS_RA, bool HAS_RB>
__global__ void epi_k(const float* __restrict__ agg, const float* __restrict__ u,
                      const float* __restrict__ dinv, const float* __restrict__ b,
                      const float* __restrict__ rA, const float* __restrict__ rB,
                      float* __restrict__ h) {
    int n = blockIdx.x * 256 + threadIdx.x;
    if (n >= NN) return;
    float dv = dinv[n];
    const float4* A = (const float4*)agg + (long)n * 4;
    const float4* U = (const float4*)u   + (long)n * 4;
    const float4* B = (const float4*)b;
    float4* H = (float4*)h + (long)n * 4;
#pragma unroll
    for (int g = 0; g < 4; g++) {
        float4 a = A[g], uu = U[g], bb = B[g];
        float4 r;
        r.x = dv * (a.x + uu.x) + bb.x;
        r.y = dv * (a.y + uu.y) + bb.y;
        r.z = dv * (a.z + uu.z) + bb.z;
        r.w = dv * (a.w + uu.w) + bb.w;
        if (HAS_RA) {
            float4 t = ((const float4*)rA)[(long)n * 4 + g];
            r.x += fmaxf(t.x, 0.f) + t.x;
            r.y += fmaxf(t.y, 0.f) + t.y;
            r.z += fmaxf(t.z, 0.f) + t.z;
            r.w += fmaxf(t.w, 0.f) + t.w;
        }
        if (HAS_RB) {
            float4 t = ((const float4*)rB)[(long)n * 4 + g];
            r.x += t.x; r.y += t.y; r.z += t.z; r.w += t.w;
        }
        H[g] = r;
    }
}

// ---------------------------------------------------------------------------
// Layer-5 GEMM: u5[n] = dinv_fd[n] * (relu(hf[n]) @ We), rows padded to 12
// ---------------------------------------------------------------------------
__global__ void gemm5_k(const float* __restrict__ hf, const float* __restrict__ We,
                        const float* __restrict__ dinv_fd, float* __restrict__ u5) {
    __shared__ float ws[160];
    if (threadIdx.x < 160) ws[threadIdx.x] = We[threadIdx.x];
    __syncthreads();
    int n = blockIdx.x * 256 + threadIdx.x;
    if (n >= NN) return;
    float xf[16];
    const float4* H = (const float4*)hf + (long)n * 4;
#pragma unroll
    for (int g = 0; g < 4; g++) {
        float4 v = H[g];
        xf[4 * g + 0] = fmaxf(v.x, 0.f);
        xf[4 * g + 1] = fmaxf(v.y, 0.f);
        xf[4 * g + 2] = fmaxf(v.z, 0.f);
        xf[4 * g + 3] = fmaxf(v.w, 0.f);
    }
    float acc[10];
#pragma unroll
    for (int f = 0; f < 10; f++) acc[f] = 0.f;
#pragma unroll
    for (int k = 0; k < 16; k++) {
        float xk = xf[k];
#pragma unroll
        for (int f = 0; f < 10; f++) acc[f] += xk * ws[k * 10 + f];
    }
    float dv = dinv_fd[n];
    long base = (long)n * 12;
#pragma unroll
    for (int f = 0; f < 10; f++) u5[base + f] = dv * acc[f];
    u5[base + 10] = 0.f;
    u5[base + 11] = 0.f;
}

// ---------------------------------------------------------------------------
// Final: o = dinv*(agg5 + u5) + be ; out = log_softmax(o) over 10 classes
// ---------------------------------------------------------------------------
__global__ void softmax_k(const float* __restrict__ agg5, const float* __restrict__ u5,
                          const float* __restrict__ dinv, const float* __restrict__ be,
                          float* __restrict__ out) {
    int n = blockIdx.x * 256 + threadIdx.x;
    if (n >= NN) return;
    float dv = dinv[n];
    long base = (long)n * 12;
    const float4* A = (const float4*)(agg5 + base);
    const float4* U = (const float4*)(u5 + base);
    float o[12];
#pragma unroll
    for (int g = 0; g < 3; g++) {
        float4 a = A[g], u = U[g];
        o[4 * g + 0] = dv * (a.x + u.x);
        o[4 * g + 1] = dv * (a.y + u.y);
        o[4 * g + 2] = dv * (a.z + u.z);
        o[4 * g + 3] = dv * (a.w + u.w);
    }
#pragma unroll
    for (int f = 0; f < 10; f++) o[f] += __ldg(be + f);
    float m = o[0];
#pragma unroll
    for (int f = 1; f < 10; f++) m = fmaxf(m, o[f]);
    float s = 0.f;
#pragma unroll
    for (int f = 0; f < 10; f++) s += expf(o[f] - m);
    float l = m + logf(s);
    long ob = (long)n * 10;
#pragma unroll
    for (int f = 0; f < 10; f++) out[ob + f] = o[f] - l;
}

// ---------------------------------------------------------------------------
// Launch
// ---------------------------------------------------------------------------
extern "C" void kernel_launch(void* const* d_in, const int* in_sizes, int n_in,
                              void* d_out, int out_size) {
    const float* xp  = (const float*)d_in[0];
    const float* xc1 = (const float*)d_in[1];
    const float* xc2 = (const float*)d_in[2];
    const float* xfd = (const float*)d_in[3];
    const int*   ep  = (const int*)d_in[4];
    const int*   ec1 = (const int*)d_in[5];
    const int*   ec2 = (const int*)d_in[6];
    const int*   efd = (const int*)d_in[7];
    const float* W1 = (const float*)d_in[8];
    const float* b1 = (const float*)d_in[9];
    const float* W2 = (const float*)d_in[10];
    const float* b2 = (const float*)d_in[11];
    const float* W3 = (const float*)d_in[12];
    const float* b3 = (const float*)d_in[13];
    const float* We = (const float*)d_in[14];
    const float* be = (const float*)d_in[15];
    float* out = (float*)d_out;

    float* S = nullptr;
    cudaGetSymbolAddress((void**)&S, g_scratch);

    int*   cnt  = (int*)(S + O_CNT);
    float* dinv = S + O_DINV;   // [parent | c1 | c2 | fd], each N
    float* u1 = S + O_U1, *u2 = S + O_U2, *u3 = S + O_U3, *u4 = S + O_U4, *u5 = S + O_U5;
    float* a1 = S + O_A1, *a2 = S + O_A2, *a3 = S + O_A3, *a4 = S + O_A4, *a5 = S + O_A5;
    float* hp = S + O_HP, *hc1 = S + O_HC1, *hc2 = S + O_HC2, *hf = S + O_HF;

    const int GN   = (NN + 255) / 256;       // 391
    const int GG   = (NN + 63) / 64;         // 1563
    const int GC   = (int)((4L * EE + 255) / 256);
    const int GS   = (EE * 4) / 256;         // 50000
    const int GZ   = (2000000 + 255) / 256;

    // 1) zero counters + all agg buffers
    zero_k<<<GZ, 256>>>(S);

    // 2) fused degree histograms (dst rows are the second half of each [2,E])
    count4_k<<<GC, 256>>>(ep + EE, ec1 + EE, ec2 + EE, efd + EE, cnt);
    dinv_k<<<(4 * NN + 255) / 256, 256>>>(cnt, dinv);

    // 3) dense GEMMs with dinv pre-scaling (u = dinv .* (x @ W))
    gemm_k<128><<<GG, 64>>>(xp,  W1, dinv + 0 * NN, u1);
    gemm_k<129><<<GG, 64>>>(xc1, W2, dinv + 1 * NN, u2);
    gemm_k<130><<<GG, 64>>>(xc2, W3, dinv + 2 * NN, u3);
    gemm_k<129><<<GG, 64>>>(xfd, W2, dinv + 3 * NN, u4);

    // 4) layer chain: scatter + epilogue
    scatter_k<16, 4><<<GS, 256>>>(ep, ep + EE, u1, a1);
    epi_k<false, false><<<GN, 256>>>(a1, u1, dinv + 0 * NN, b1, nullptr, nullptr, hp);

    scatter_k<16, 4><<<GS, 256>>>(ec1, ec1 + EE, u2, a2);
    epi_k<true, false><<<GN, 256>>>(a2, u2, dinv + 1 * NN, b2, hp, nullptr, hc1);

    scatter_k<16, 4><<<GS, 256>>>(ec2, ec2 + EE, u3, a3);
    epi_k<true, false><<<GN, 256>>>(a3, u3, dinv + 2 * NN, b3, hc1, nullptr, hc2);

    scatter_k<16, 4><<<GS, 256>>>(efd, efd + EE, u4, a4);
    epi_k<true, true><<<GN, 256>>>(a4, u4, dinv + 3 * NN, b2, hc2, hc1, hf);

    // 5) final conv on relu(hf) with We, then log_softmax
    gemm5_k<<<GN, 256>>>(hf, We, dinv + 3 * NN, u5);
    scatter_k<12, 3><<<GS, 256>>>(efd, efd + EE, u5, a5);
    softmax_k<<<GN, 256>>>(a5, u5, dinv + 3 * NN, be, out);
}